// round 14
// baseline (speedup 1.0000x reference)
#include <cuda_runtime.h>
#include <cuda_fp16.h>
#include <cstdint>

#define N_NODES 30000
#define N_EDGES 150000
#define N_REL   10
#define DIM     256

#define BM 128
#define BN 64
#define BK 32
#define NKB (DIM / BK)          // 8 k-steps
#define THREADS 256
#define NSTAGE 4
#define NB ((N_EDGES + 255) / 256)                      // 586 sort blocks
#define SELF_TILES ((N_NODES + BM - 1) / BM)            // 235
#define MAX_TILES  ((N_EDGES + BM - 1) / BM + N_REL)    // 1182 worst case
#define GRID_X (SELF_TILES + 2 * MAX_TILES)

// byte strides (odd multiples of 16B -> ldmatrix conflict-free)
#define PA_B 80      // A row: 64B data (32 fp16) + 16B pad
#define PB_B 80      // B n-row: 64B data (32 k fp16) + 16B pad

#define A_BYTES (BM * PA_B)      // 10240
#define B_BYTES (BN * PB_B)      // 5120
#define STAGE_BYTES (A_BYTES + B_BYTES)          // 15360
#define DSMEM_BYTES (NSTAGE * STAGE_BYTES)       // 61440 -> 3 CTAs = 180KB

#define XV (N_NODES * DIM / 4)          // float4 chunks of x
#define XVB ((XV + 255) / 256)          // 7500 x-convert blocks
#define WTB (21 * 64)                   // 1344 W-transpose tiles (32x32)

// ---------------- scratch ----------------
__device__ int g_bh[N_REL * NB];      // per-block histograms
__device__ int g_boff[N_REL * NB];    // per-block scatter bases (incl. rel base)
__device__ int g_off[N_REL + 1];
__device__ int g_tile_start[N_REL + 1];
__device__ int g_sorted[N_EDGES];
__device__ __half g_xh[(size_t)N_NODES * DIM];   // x in fp16 (RNE)
__device__ __half g_Wt[21 * DIM * DIM];          // W fp16, n-major: [m][n][k]

// ---------------- helpers ----------------
__device__ __forceinline__ void cp16(uint32_t saddr, const void* gmem) {
    asm volatile("cp.async.cg.shared.global [%0], [%1], 16;\n" :: "r"(saddr), "l"(gmem));
}
__device__ __forceinline__ void cp_commit() {
    asm volatile("cp.async.commit_group;\n" ::: "memory");
}
template <int N>
__device__ __forceinline__ void cp_wait() {
    asm volatile("cp.async.wait_group %0;\n" :: "n"(N) : "memory");
}
__device__ __forceinline__ void ldsm_x4(uint32_t* r, uint32_t addr) {
    asm volatile("ldmatrix.sync.aligned.m8n8.x4.shared.b16 {%0,%1,%2,%3}, [%4];"
                 : "=r"(r[0]), "=r"(r[1]), "=r"(r[2]), "=r"(r[3]) : "r"(addr));
}

// ---------------- kernel 1: x convert + fused hist + W n-major transpose ----
__global__ void k_pre(const float* __restrict__ x,
                      const float* __restrict__ W_self,
                      const float* __restrict__ W_fwd,
                      const float* __restrict__ W_rev,
                      const int* __restrict__ rel) {
    __shared__ int h[N_REL];
    __shared__ __half tile[32][33];

    if (blockIdx.x < XVB) {
        const bool do_hist = (blockIdx.x < NB);
        if (do_hist) {
            if (threadIdx.x < N_REL) h[threadIdx.x] = 0;
            __syncthreads();
            int e = blockIdx.x * 256 + threadIdx.x;
            if (e < N_EDGES) {
                int r = rel[e];
                unsigned m = __match_any_sync(__activemask(), r);
                if ((threadIdx.x & 31) == __ffs(m) - 1) atomicAdd(&h[r], __popc(m));
            }
        }
        int i = blockIdx.x * 256 + threadIdx.x;
        if (i < XV) {
            float4 v = reinterpret_cast<const float4*>(x)[i];
            __half2 lo = __floats2half2_rn(v.x, v.y);
            __half2 hi = __floats2half2_rn(v.z, v.w);
            uint2 o;
            o.x = *reinterpret_cast<uint32_t*>(&lo);
            o.y = *reinterpret_cast<uint32_t*>(&hi);
            reinterpret_cast<uint2*>(g_xh)[i] = o;
        }
        if (do_hist) {
            __syncthreads();
            if (threadIdx.x < N_REL) g_bh[threadIdx.x * NB + blockIdx.x] = h[threadIdx.x];
        }
    } else {
        // W transpose: [k][n] fp32 -> [n][k] fp16, 32x32 tiles, 21 matrices
        int idx = blockIdx.x - XVB;
        int m = idx >> 6, t = idx & 63;
        int tn = t >> 3, tk = t & 7;
        const float* src = (m == 0) ? W_self
                         : (m <= 10) ? W_fwd + (size_t)(m - 1) * DIM * DIM
                                     : W_rev + (size_t)(m - 11) * DIM * DIM;
        int tx = threadIdx.x & 31, ty = threadIdx.x >> 5;   // 32 x 8
        #pragma unroll
        for (int j = 0; j < 4; j++) {
            int k = tk * 32 + ty + j * 8;
            int n = tn * 32 + tx;
            tile[ty + j * 8][tx] = __float2half_rn(src[(size_t)k * DIM + n]);
        }
        __syncthreads();
        __half* dst = g_Wt + (size_t)m * DIM * DIM;
        #pragma unroll
        for (int j = 0; j < 4; j++) {
            int n = tn * 32 + ty + j * 8;
            int k = tk * 32 + tx;
            dst[(size_t)n * DIM + k] = tile[tx][ty + j * 8];
        }
    }
}

// ---------------- kernel 2: scan ----------------
__global__ void k_scan() {   // one block, 320 threads: warp w owns relation w
    __shared__ int s_tot[N_REL];
    __shared__ int s_base[N_REL];
    int w = threadIdx.x >> 5, lane = threadIdx.x & 31;
    if (w < N_REL) {
        int sum = 0;
        for (int i = lane; i < NB; i += 32) sum += g_bh[w * NB + i];
        #pragma unroll
        for (int o = 16; o; o >>= 1) sum += __shfl_xor_sync(~0u, sum, o);
        if (!lane) s_tot[w] = sum;
    }
    __syncthreads();
    if (threadIdx.x == 0) {
        int off = 0, ts = 0;
        for (int r = 0; r < N_REL; r++) {
            s_base[r] = off; g_off[r] = off; g_tile_start[r] = ts;
            off += s_tot[r]; ts += (s_tot[r] + BM - 1) / BM;
        }
        g_off[N_REL] = off; g_tile_start[N_REL] = ts;
    }
    __syncthreads();
    if (w < N_REL) {
        int run = s_base[w];
        for (int base = 0; base < NB; base += 32) {
            int i = base + lane;
            int v = (i < NB) ? g_bh[w * NB + i] : 0;
            int x = v;
            #pragma unroll
            for (int o = 1; o < 32; o <<= 1) {
                int y = __shfl_up_sync(~0u, x, o);
                if (lane >= o) x += y;
            }
            if (i < NB) g_boff[w * NB + i] = run + x - v;
            run += __shfl_sync(~0u, x, 31);
        }
    }
}

// ---------------- kernel 3: scatter ----------------
__global__ void k_scatter(const int* __restrict__ rel) {
    __shared__ int cur[N_REL];
    if (threadIdx.x < N_REL)
        cur[threadIdx.x] = g_boff[threadIdx.x * NB + blockIdx.x];
    __syncthreads();
    int e = blockIdx.x * 256 + threadIdx.x;
    if (e < N_EDGES) {
        int lane = threadIdx.x & 31;
        int r = rel[e];
        unsigned m = __match_any_sync(__activemask(), r);
        int leader = __ffs(m) - 1;
        int rank = __popc(m & ((1u << lane) - 1));
        int base = 0;
        if (lane == leader) base = atomicAdd(&cur[r], __popc(m));
        base = __shfl_sync(m, base, leader);
        g_sorted[base + rank] = e;
    }
}

// ---------------- kernel 4: fused grouped gather-GEMM (3 CTAs/SM) ----------
// grid (GRID_X, 4): blockIdx.y = N-quarter, 64 cols each.
__global__ __launch_bounds__(THREADS, 3)
void k_gemm(const float* __restrict__ b_self,
            const float* __restrict__ b_fwd,
            const float* __restrict__ b_rev,
            const int* __restrict__ dep,
            const int* __restrict__ gov,
            float* __restrict__ out)
{
    extern __shared__ char smem[];
    __shared__ int s_src[BM];
    __shared__ int s_dst[BM];
    __shared__ float s_bias[BN];

    const int tid  = threadIdx.x;
    const int lane = tid & 31;
    const int warp = tid >> 5;
    const int wm   = warp >> 1;   // 0..3 : 32-row band
    const int wn   = warp & 1;    // 0..1 : 32-col band
    const int nbase = blockIdx.y * BN;

    // ---- tile resolve ----
    int t = blockIdx.x;
    const float* bias;
    const __half* Wt;   // n-major weights, offset to nbase
    if (t < SELF_TILES) {
        Wt = g_Wt + (size_t)nbase * DIM;
        bias = b_self;
        if (tid < BM) {
            int row = t * BM + tid;
            s_src[tid] = (row < N_NODES) ? row : 0;
            s_dst[tid] = (row < N_NODES) ? row : -1;
        }
    } else {
        int T = g_tile_start[N_REL];
        int tm = t - SELF_TILES;
        if (tm >= 2 * T) return;                      // uniform early exit
        int mode = (tm < T) ? 1 : 2;
        int tt = (mode == 1) ? tm : tm - T;
        int g = 0;
        while (tt >= g_tile_start[g + 1]) g++;
        int ebase = g_off[g] + (tt - g_tile_start[g]) * BM;
        int ecnt  = g_off[g + 1] - ebase;
        Wt   = g_Wt + (size_t)(1 + (mode == 2 ? N_REL : 0) + g) * DIM * DIM
                    + (size_t)nbase * DIM;
        bias = ((mode == 1) ? b_fwd : b_rev) + g * DIM;
        if (tid < BM) {
            if (tid < ecnt) {
                int e = g_sorted[ebase + tid];
                s_src[tid] = (mode == 1) ? gov[e] : dep[e];
                s_dst[tid] = (mode == 1) ? dep[e] : gov[e];
            } else {
                s_src[tid] = 0; s_dst[tid] = -1;
            }
        }
    }
    if (tid < BN) s_bias[tid] = bias[nbase + tid];
    __syncthreads();

    const uint32_t sbase = (uint32_t)__cvta_generic_to_shared(smem);

    // ---- staging: A = 128 rows x 32 fp16 (gathered); B = 64 n-rows x 32 k
    auto prefetch = [&](int stg, int kb) {
        uint32_t As = sbase + stg * STAGE_BYTES;
        uint32_t Bs = As + A_BYTES;
        #pragma unroll
        for (int j = 0; j < 2; j++) {                 // 512 16B-segs of A
            int i = tid + THREADS * j;
            int row = i >> 2, seg = i & 3;
            cp16(As + row * PA_B + seg * 16,
                 g_xh + (size_t)s_src[row] * DIM + kb * BK + seg * 8);
        }
        {                                             // 256 16B-segs of B
            int row = tid >> 2, seg = tid & 3;        // n-row, k-seg
            if (row < BN)
                cp16(Bs + row * PB_B + seg * 16,
                     Wt + (size_t)row * DIM + kb * BK + seg * 8);
        }
    };

    float acc[2][4][4];
    #pragma unroll
    for (int i = 0; i < 2; i++)
        #pragma unroll
        for (int j = 0; j < 4; j++)
            #pragma unroll
            for (int k = 0; k < 4; k++) acc[i][j][k] = 0.0f;

    // ldmatrix per-lane address parts (both non-trans)
    const uint32_t rowA = (wm * 32 + (lane & 15)) * PA_B + (lane >> 4) * 16;
    const uint32_t rowB = (wn * 32 + (lane >> 4) * 8 + (lane & 7)) * PB_B
                          + ((lane >> 3) & 1) * 16;

    prefetch(0, 0); cp_commit();
    prefetch(1, 1); cp_commit();
    prefetch(2, 2); cp_commit();

    #pragma unroll 1
    for (int kb = 0; kb < NKB; kb++) {
        if (kb < NKB - 2)       cp_wait<2>();
        else if (kb == NKB - 2) cp_wait<1>();
        else                    cp_wait<0>();
        __syncthreads();
        if (kb + 3 < NKB) {
            prefetch((kb + 3) % NSTAGE, kb + 3);
            cp_commit();
        }

        uint32_t As = sbase + (kb % NSTAGE) * STAGE_BYTES;
        uint32_t Bs = As + A_BYTES;

        #pragma unroll
        for (int kk = 0; kk < 2; kk++) {     // two k16 chunks per BK=32
            uint32_t a[2][4];
            ldsm_x4(a[0], As + rowA + kk * 32);             // rows wm*32..+15
            ldsm_x4(a[1], As + rowA + 16 * PA_B + kk * 32); // rows +16..+31
            uint32_t b[2][4];                               // 2 groups of 16 n-cols
            #pragma unroll
            for (int ntg = 0; ntg < 2; ntg++)
                ldsm_x4(b[ntg], Bs + rowB + ntg * (16 * PB_B) + kk * 32);
            #pragma unroll
            for (int mt = 0; mt < 2; mt++)
                #pragma unroll
                for (int nt = 0; nt < 4; nt++)
                    asm volatile(
                        "mma.sync.aligned.m16n8k16.row.col.f32.f16.f16.f32 "
                        "{%0,%1,%2,%3},{%4,%5,%6,%7},{%8,%9},{%0,%1,%2,%3};"
                        : "+f"(acc[mt][nt][0]), "+f"(acc[mt][nt][1]),
                          "+f"(acc[mt][nt][2]), "+f"(acc[mt][nt][3])
                        : "r"(a[mt][0]), "r"(a[mt][1]), "r"(a[mt][2]), "r"(a[mt][3]),
                          "r"(b[nt >> 1][(nt & 1) * 2]),
                          "r"(b[nt >> 1][(nt & 1) * 2 + 1]));
        }
    }

    // ---- epilogue: pair lanes (lane^1 shares the same output row) and issue
    // 128-bit red.global.add.v4.f32 into pre-zeroed out.
    const int gq = lane >> 2;
    const int tg = lane & 3;
    #pragma unroll
    for (int mt = 0; mt < 2; mt++) {
        #pragma unroll
        for (int half = 0; half < 2; half++) {
            int rl = wm * 32 + mt * 16 + gq + half * 8;
            int d  = s_dst[rl];
            #pragma unroll
            for (int nt = 0; nt < 4; nt++) {
                int cl = wn * 32 + nt * 8 + tg * 2;       // local col in [0,64)
                float v0 = acc[mt][nt][half * 2 + 0] + s_bias[cl];
                float v1 = acc[mt][nt][half * 2 + 1] + s_bias[cl + 1];
                float s0 = __shfl_xor_sync(0xFFFFFFFFu, v0, 1);
                float s1 = __shfl_xor_sync(0xFFFFFFFFu, v1, 1);
                if (d >= 0 && ((tg ^ nt) & 1) == 0) {
                    float a0, a1, a2, a3;
                    if (tg & 1) { a0 = s0; a1 = s1; a2 = v0; a3 = v1; }
                    else        { a0 = v0; a1 = v1; a2 = s0; a3 = s1; }
                    int c4 = nbase + wn * 32 + nt * 8 + (tg >> 1) * 4;
                    asm volatile("red.global.add.v4.f32 [%0], {%1,%2,%3,%4};"
                                 :: "l"(&out[(size_t)d * DIM + c4]),
                                    "f"(a0), "f"(a1), "f"(a2), "f"(a3)
                                 : "memory");
                }
            }
        }
    }
}

// ---------------- launch ----------------
extern "C" void kernel_launch(void* const* d_in, const int* in_sizes, int n_in,
                              void* d_out, int out_size)
{
    const float* x      = (const float*)d_in[0];
    const float* W_self = (const float*)d_in[1];
    const float* b_self = (const float*)d_in[2];
    const float* W_fwd  = (const float*)d_in[3];
    const float* b_fwd  = (const float*)d_in[4];
    const float* W_rev  = (const float*)d_in[5];
    const float* b_rev  = (const float*)d_in[6];
    const int*   dep    = (const int*)d_in[7];
    const int*   rel    = (const int*)d_in[8];
    const int*   gov    = (const int*)d_in[9];
    float* out = (float*)d_out;

    static bool attr_set = false;
    if (!attr_set) {
        cudaFuncSetAttribute(k_gemm, cudaFuncAttributeMaxDynamicSharedMemorySize,
                             DSMEM_BYTES);
        attr_set = true;
    }

    // k_gemm is the 4th kernel launch — the slot ncu's window captures.
    cudaMemsetAsync(d_out, 0, (size_t)out_size * sizeof(float));
    k_pre<<<XVB + WTB, 256>>>(x, W_self, W_fwd, W_rev, rel);
    k_scan<<<1, 320>>>();
    k_scatter<<<NB, 256>>>(rel);

    // one fused launch: self + fwd + rev tiles x 4 N-quarters
    k_gemm<<<dim3(GRID_X, 4), THREADS, DSMEM_BYTES>>>(
        b_self, b_fwd, b_rev, dep, gov, out);
}

// round 15
// speedup vs baseline: 1.2972x; 1.2972x over previous
#include <cuda_runtime.h>
#include <cuda_fp16.h>
#include <cstdint>

#define N_NODES 30000
#define N_EDGES 150000
#define N_REL   10
#define DIM     256

#define BM 128
#define BN 128
#define BK 64
#define NKB (DIM / BK)          // 4 k-steps
#define THREADS 256
#define NSTAGE 3
#define NB ((N_EDGES + 255) / 256)                      // 586 sort blocks
#define SELF_TILES ((N_NODES + BM - 1) / BM)            // 235
#define MAX_TILES  ((N_EDGES + BM - 1) / BM + N_REL)    // 1182 worst case
#define GRID_X (SELF_TILES + 2 * MAX_TILES)

// byte strides (odd multiples of 16B -> ldmatrix conflict-free)
#define PA_B 144     // A row: 128B data (64 fp16) + 16B pad
#define PB_B 144     // B n-row: 128B data (64 fp16 of k) + 16B pad

#define A_BYTES (BM * PA_B)      // 18432
#define B_BYTES (BN * PB_B)      // 18432
#define STAGE_BYTES (A_BYTES + B_BYTES)          // 36864
#define DSMEM_BYTES (NSTAGE * STAGE_BYTES)       // 110592

#define XV (N_NODES * DIM / 4)          // float4 chunks of x
#define XVB ((XV + 255) / 256)          // 7500 x-convert blocks
#define WTB (21 * 64)                   // 1344 W-transpose tiles (32x32)

// ---------------- scratch ----------------
__device__ int g_bh[N_REL * NB];      // per-block histograms
__device__ int g_boff[N_REL * NB];    // per-block scatter bases (incl. rel base)
__device__ int g_off[N_REL + 1];
__device__ int g_tile_start[N_REL + 1];
__device__ int g_sorted[N_EDGES];
__device__ __half g_xh[(size_t)N_NODES * DIM];   // x in fp16 (RNE)
__device__ __half g_Wt[21 * DIM * DIM];          // W fp16, n-major: [m][n][k]

// ---------------- helpers ----------------
__device__ __forceinline__ void cp16(uint32_t saddr, const void* gmem) {
    asm volatile("cp.async.cg.shared.global [%0], [%1], 16;\n" :: "r"(saddr), "l"(gmem));
}
__device__ __forceinline__ void cp_commit() {
    asm volatile("cp.async.commit_group;\n" ::: "memory");
}
template <int N>
__device__ __forceinline__ void cp_wait() {
    asm volatile("cp.async.wait_group %0;\n" :: "n"(N) : "memory");
}
__device__ __forceinline__ void ldsm_x4(uint32_t* r, uint32_t addr) {
    asm volatile("ldmatrix.sync.aligned.m8n8.x4.shared.b16 {%0,%1,%2,%3}, [%4];"
                 : "=r"(r[0]), "=r"(r[1]), "=r"(r[2]), "=r"(r[3]) : "r"(addr));
}

// ---------------- kernel A: per-block relation histogram ----------------
__global__ void k_hist(const int* __restrict__ rel) {
    __shared__ int h[N_REL];
    if (threadIdx.x < N_REL) h[threadIdx.x] = 0;
    __syncthreads();
    int e = blockIdx.x * 256 + threadIdx.x;
    if (e < N_EDGES) {
        int r = rel[e];
        unsigned m = __match_any_sync(__activemask(), r);
        if ((threadIdx.x & 31) == __ffs(m) - 1) atomicAdd(&h[r], __popc(m));
    }
    __syncthreads();
    if (threadIdx.x < N_REL) g_bh[threadIdx.x * NB + blockIdx.x] = h[threadIdx.x];
}

// ---------------- kernel B (side stream): scan ----------------
__global__ void k_scan() {   // one block, 320 threads: warp w owns relation w
    __shared__ int s_tot[N_REL];
    __shared__ int s_base[N_REL];
    int w = threadIdx.x >> 5, lane = threadIdx.x & 31;
    if (w < N_REL) {
        int sum = 0;
        for (int i = lane; i < NB; i += 32) sum += g_bh[w * NB + i];
        #pragma unroll
        for (int o = 16; o; o >>= 1) sum += __shfl_xor_sync(~0u, sum, o);
        if (!lane) s_tot[w] = sum;
    }
    __syncthreads();
    if (threadIdx.x == 0) {
        int off = 0, ts = 0;
        for (int r = 0; r < N_REL; r++) {
            s_base[r] = off; g_off[r] = off; g_tile_start[r] = ts;
            off += s_tot[r]; ts += (s_tot[r] + BM - 1) / BM;
        }
        g_off[N_REL] = off; g_tile_start[N_REL] = ts;
    }
    __syncthreads();
    if (w < N_REL) {
        int run = s_base[w];
        for (int base = 0; base < NB; base += 32) {
            int i = base + lane;
            int v = (i < NB) ? g_bh[w * NB + i] : 0;
            int x = v;
            #pragma unroll
            for (int o = 1; o < 32; o <<= 1) {
                int y = __shfl_up_sync(~0u, x, o);
                if (lane >= o) x += y;
            }
            if (i < NB) g_boff[w * NB + i] = run + x - v;
            run += __shfl_sync(~0u, x, 31);
        }
    }
}

// ---------------- kernel C (side stream): scatter ----------------
__global__ void k_scatter(const int* __restrict__ rel) {
    __shared__ int cur[N_REL];
    if (threadIdx.x < N_REL)
        cur[threadIdx.x] = g_boff[threadIdx.x * NB + blockIdx.x];
    __syncthreads();
    int e = blockIdx.x * 256 + threadIdx.x;
    if (e < N_EDGES) {
        int lane = threadIdx.x & 31;
        int r = rel[e];
        unsigned m = __match_any_sync(__activemask(), r);
        int leader = __ffs(m) - 1;
        int rank = __popc(m & ((1u << lane) - 1));
        int base = 0;
        if (lane == leader) base = atomicAdd(&cur[r], __popc(m));
        base = __shfl_sync(m, base, leader);
        g_sorted[base + rank] = e;
    }
}

// ---------------- kernel D (main stream): x fp16 convert + W n-major transpose
__global__ void k_conv(const float* __restrict__ x,
                       const float* __restrict__ W_self,
                       const float* __restrict__ W_fwd,
                       const float* __restrict__ W_rev) {
    __shared__ __half tile[32][33];
    if (blockIdx.x < XVB) {
        int i = blockIdx.x * 256 + threadIdx.x;
        if (i < XV) {
            float4 v = reinterpret_cast<const float4*>(x)[i];
            __half2 lo = __floats2half2_rn(v.x, v.y);
            __half2 hi = __floats2half2_rn(v.z, v.w);
            uint2 o;
            o.x = *reinterpret_cast<uint32_t*>(&lo);
            o.y = *reinterpret_cast<uint32_t*>(&hi);
            reinterpret_cast<uint2*>(g_xh)[i] = o;
        }
    } else {
        // W transpose: [k][n] fp32 -> [n][k] fp16, 32x32 tiles, 21 matrices
        int idx = blockIdx.x - XVB;
        int m = idx >> 6, t = idx & 63;
        int tn = t >> 3, tk = t & 7;
        const float* src = (m == 0) ? W_self
                         : (m <= 10) ? W_fwd + (size_t)(m - 1) * DIM * DIM
                                     : W_rev + (size_t)(m - 11) * DIM * DIM;
        int tx = threadIdx.x & 31, ty = threadIdx.x >> 5;   // 32 x 8
        #pragma unroll
        for (int j = 0; j < 4; j++) {
            int k = tk * 32 + ty + j * 8;
            int n = tn * 32 + tx;
            tile[ty + j * 8][tx] = __float2half_rn(src[(size_t)k * DIM + n]);
        }
        __syncthreads();
        __half* dst = g_Wt + (size_t)m * DIM * DIM;
        #pragma unroll
        for (int j = 0; j < 4; j++) {
            int n = tn * 32 + ty + j * 8;
            int k = tk * 32 + tx;
            dst[(size_t)n * DIM + k] = tile[tx][ty + j * 8];
        }
    }
}

// ---------------- kernel E: fused grouped gather-GEMM (round-12 version) ----
__global__ __launch_bounds__(THREADS, 2)
void k_gemm(const float* __restrict__ b_self,
            const float* __restrict__ b_fwd,
            const float* __restrict__ b_rev,
            const int* __restrict__ dep,
            const int* __restrict__ gov,
            float* __restrict__ out)
{
    extern __shared__ char smem[];
    __shared__ int s_src[BM];
    __shared__ int s_dst[BM];

    const int tid  = threadIdx.x;
    const int lane = tid & 31;
    const int warp = tid >> 5;
    const int wm   = warp >> 1;   // 0..3 : 32-row band
    const int wn   = warp & 1;    // 0..1 : 64-col band
    const int nbase = blockIdx.y * BN;

    // ---- tile resolve ----
    int t = blockIdx.x;
    const float* bias;
    const __half* Wt;   // n-major weights, offset to nbase
    if (t < SELF_TILES) {
        Wt = g_Wt + (size_t)nbase * DIM;
        bias = b_self;
        if (tid < BM) {
            int row = t * BM + tid;
            s_src[tid] = (row < N_NODES) ? row : 0;
            s_dst[tid] = (row < N_NODES) ? row : -1;
        }
    } else {
        int T = g_tile_start[N_REL];
        int tm = t - SELF_TILES;
        if (tm >= 2 * T) return;                      // uniform early exit
        int mode = (tm < T) ? 1 : 2;
        int tt = (mode == 1) ? tm : tm - T;
        int g = 0;
        while (tt >= g_tile_start[g + 1]) g++;
        int ebase = g_off[g] + (tt - g_tile_start[g]) * BM;
        int ecnt  = g_off[g + 1] - ebase;
        Wt   = g_Wt + (size_t)(1 + (mode == 2 ? N_REL : 0) + g) * DIM * DIM
                    + (size_t)nbase * DIM;
        bias = ((mode == 1) ? b_fwd : b_rev) + g * DIM;
        if (tid < BM) {
            if (tid < ecnt) {
                int e = g_sorted[ebase + tid];
                s_src[tid] = (mode == 1) ? gov[e] : dep[e];
                s_dst[tid] = (mode == 1) ? dep[e] : gov[e];
            } else {
                s_src[tid] = 0; s_dst[tid] = -1;
            }
        }
    }
    __syncthreads();

    const uint32_t sbase = (uint32_t)__cvta_generic_to_shared(smem);

    // ---- staging: A = 128 rows x 64 fp16 (gathered); B = 128 n-rows x 64 k
    auto prefetch = [&](int stg, int kb) {
        uint32_t As = sbase + stg * STAGE_BYTES;
        uint32_t Bs = As + A_BYTES;
        #pragma unroll
        for (int j = 0; j < 4; j++) {                 // 1024 16B-segs of A
            int i = tid + THREADS * j;
            int row = i >> 3, seg = i & 7;
            cp16(As + row * PA_B + seg * 16,
                 g_xh + (size_t)s_src[row] * DIM + kb * BK + seg * 8);
        }
        #pragma unroll
        for (int j = 0; j < 4; j++) {                 // 1024 16B-segs of B
            int i = tid + THREADS * j;
            int row = i >> 3, seg = i & 7;            // n-row, k-seg
            cp16(Bs + row * PB_B + seg * 16,
                 Wt + (size_t)row * DIM + kb * BK + seg * 8);
        }
    };

    float acc[2][8][4];
    #pragma unroll
    for (int i = 0; i < 2; i++)
        #pragma unroll
        for (int j = 0; j < 8; j++)
            #pragma unroll
            for (int k = 0; k < 4; k++) acc[i][j][k] = 0.0f;

    // ldmatrix per-lane address parts (both non-trans)
    const uint32_t rowA = (wm * 32 + (lane & 15)) * PA_B + (lane >> 4) * 16;
    const uint32_t rowB = (wn * 64 + (lane >> 4) * 8 + (lane & 7)) * PB_B
                          + ((lane >> 3) & 1) * 16;

    prefetch(0, 0); cp_commit();
    prefetch(1, 1); cp_commit();

    #pragma unroll
    for (int kb = 0; kb < NKB; kb++) {
        if (kb + 1 < NKB) cp_wait<1>(); else cp_wait<0>();
        __syncthreads();
        if (kb + 2 < NKB) {
            prefetch((kb + 2) % NSTAGE, kb + 2);
            cp_commit();
        }

        uint32_t As = sbase + (kb % NSTAGE) * STAGE_BYTES;
        uint32_t Bs = As + A_BYTES;

        #pragma unroll
        for (int kk = 0; kk < 4; kk++) {     // four k16 chunks per BK=64
            uint32_t a[2][4];
            ldsm_x4(a[0], As + rowA + kk * 32);             // rows wm*32..+15
            ldsm_x4(a[1], As + rowA + 16 * PA_B + kk * 32); // rows +16..+31
            uint32_t b[4][4];                               // 4 groups of 16 n-cols
            #pragma unroll
            for (int ntg = 0; ntg < 4; ntg++)
                ldsm_x4(b[ntg], Bs + rowB + ntg * (16 * PB_B) + kk * 32);
            #pragma unroll
            for (int mt = 0; mt < 2; mt++)
                #pragma unroll
                for (int nt = 0; nt < 8; nt++)
                    asm volatile(
                        "mma.sync.aligned.m16n8k16.row.col.f32.f16.f16.f32 "
                        "{%0,%1,%2,%3},{%4,%5,%6,%7},{%8,%9},{%0,%1,%2,%3};"
                        : "+f"(acc[mt][nt][0]), "+f"(acc[mt][nt][1]),
                          "+f"(acc[mt][nt][2]), "+f"(acc[mt][nt][3])
                        : "r"(a[mt][0]), "r"(a[mt][1]), "r"(a[mt][2]), "r"(a[mt][3]),
                          "r"(b[nt >> 1][(nt & 1) * 2]),
                          "r"(b[nt >> 1][(nt & 1) * 2 + 1]));
        }
    }

    // ---- epilogue: pair lanes (lane^1 shares the same output row) and issue
    // 128-bit red.global.add.v4.f32 into pre-zeroed out.
    const int gq = lane >> 2;
    const int tg = lane & 3;
    #pragma unroll
    for (int mt = 0; mt < 2; mt++) {
        #pragma unroll
        for (int half = 0; half < 2; half++) {
            int rl = wm * 32 + mt * 16 + gq + half * 8;
            int d  = s_dst[rl];
            #pragma unroll
            for (int nt = 0; nt < 8; nt++) {
                int c  = nbase + wn * 64 + nt * 8 + tg * 2;
                float v0 = acc[mt][nt][half * 2 + 0] + __ldg(&bias[c]);
                float v1 = acc[mt][nt][half * 2 + 1] + __ldg(&bias[c + 1]);
                float s0 = __shfl_xor_sync(0xFFFFFFFFu, v0, 1);
                float s1 = __shfl_xor_sync(0xFFFFFFFFu, v1, 1);
                if (d >= 0 && ((tg ^ nt) & 1) == 0) {
                    float a0, a1, a2, a3;
                    if (tg & 1) { a0 = s0; a1 = s1; a2 = v0; a3 = v1; }
                    else        { a0 = v0; a1 = v1; a2 = s0; a3 = s1; }
                    int c4 = nbase + wn * 64 + nt * 8 + (tg >> 1) * 4;
                    asm volatile("red.global.add.v4.f32 [%0], {%1,%2,%3,%4};"
                                 :: "l"(&out[(size_t)d * DIM + c4]),
                                    "f"(a0), "f"(a1), "f"(a2), "f"(a3)
                                 : "memory");
                }
            }
        }
    }
}

// ---------------- launch (stream fork/join inside the captured graph) -------
extern "C" void kernel_launch(void* const* d_in, const int* in_sizes, int n_in,
                              void* d_out, int out_size)
{
    const float* x      = (const float*)d_in[0];
    const float* W_self = (const float*)d_in[1];
    const float* b_self = (const float*)d_in[2];
    const float* W_fwd  = (const float*)d_in[3];
    const float* b_fwd  = (const float*)d_in[4];
    const float* W_rev  = (const float*)d_in[5];
    const float* b_rev  = (const float*)d_in[6];
    const int*   dep    = (const int*)d_in[7];
    const int*   rel    = (const int*)d_in[8];
    const int*   gov    = (const int*)d_in[9];
    float* out = (float*)d_out;

    static bool init_done = false;
    static cudaStream_t s1;
    static cudaEvent_t evFork, evJoin;
    if (!init_done) {
        cudaFuncSetAttribute(k_gemm, cudaFuncAttributeMaxDynamicSharedMemorySize,
                             DSMEM_BYTES);
        cudaStreamCreateWithFlags(&s1, cudaStreamNonBlocking);
        cudaEventCreateWithFlags(&evFork, cudaEventDisableTiming);
        cudaEventCreateWithFlags(&evJoin, cudaEventDisableTiming);
        init_done = true;
    }

    // main stream: memset + hist, then fork
    cudaMemsetAsync(d_out, 0, (size_t)out_size * sizeof(float));
    k_hist<<<NB, 256>>>(rel);
    cudaEventRecord(evFork, 0);
    cudaStreamWaitEvent(s1, evFork, 0);

    // side stream: scan + scatter   ||   main stream: convert/transpose
    k_scan<<<1, 320, 0, s1>>>();
    k_scatter<<<NB, 256, 0, s1>>>(rel);
    k_conv<<<XVB + WTB, 256>>>(x, W_self, W_fwd, W_rev);

    // join, then GEMM
    cudaEventRecord(evJoin, s1);
    cudaStreamWaitEvent(0, evJoin, 0);
    k_gemm<<<dim3(GRID_X, 2), THREADS, DSMEM_BYTES>>>(
        b_self, b_fwd, b_rev, dep, gov, out);
}

// round 16
// speedup vs baseline: 1.3417x; 1.0343x over previous
#include <cuda_runtime.h>
#include <cuda_fp16.h>
#include <cstdint>

#define N_NODES 30000
#define N_EDGES 150000
#define N_REL   10
#define DIM     256

#define BM 128
#define BN 128
#define BK 64
#define NKB (DIM / BK)          // 4 k-steps
#define THREADS 256
#define NSTAGE 3
#define NB ((N_EDGES + 255) / 256)                      // 586 sort blocks
#define SELF_TILES ((N_NODES + BM - 1) / BM)            // 235
#define MAX_TILES  ((N_EDGES + BM - 1) / BM + N_REL)    // 1182 worst case

// byte strides (odd multiples of 16B -> ldmatrix conflict-free)
#define PA_B 144     // A row: 128B data (64 fp16) + 16B pad
#define PB_B 144     // B n-row: 128B data (64 fp16 of k) + 16B pad

#define A_BYTES (BM * PA_B)      // 18432
#define B_BYTES (BN * PB_B)      // 18432
#define STAGE_BYTES (A_BYTES + B_BYTES)          // 36864
#define DSMEM_BYTES (NSTAGE * STAGE_BYTES)       // 110592

#define XV (N_NODES * DIM / 4)          // float4 chunks of x
#define XVB ((XV + 255) / 256)          // 7500 x-convert blocks
#define WTB (21 * 64)                   // 1344 W-transpose tiles (32x32)

// ---------------- scratch ----------------
__device__ int g_bh[N_REL * NB];      // per-block histograms
__device__ int g_boff[N_REL * NB];    // per-block scatter bases (incl. rel base)
__device__ int g_off[N_REL + 1];
__device__ int g_tile_start[N_REL + 1];
__device__ int g_sorted[N_EDGES];
__device__ __half g_xh[(size_t)N_NODES * DIM];   // x in fp16 (RNE)
__device__ __half g_Wt[21 * DIM * DIM];          // W fp16, n-major: [m][n][k]

// ---------------- helpers ----------------
__device__ __forceinline__ void cp16(uint32_t saddr, const void* gmem) {
    asm volatile("cp.async.cg.shared.global [%0], [%1], 16;\n" :: "r"(saddr), "l"(gmem));
}
__device__ __forceinline__ void cp_commit() {
    asm volatile("cp.async.commit_group;\n" ::: "memory");
}
template <int N>
__device__ __forceinline__ void cp_wait() {
    asm volatile("cp.async.wait_group %0;\n" :: "n"(N) : "memory");
}
__device__ __forceinline__ void ldsm_x4(uint32_t* r, uint32_t addr) {
    asm volatile("ldmatrix.sync.aligned.m8n8.x4.shared.b16 {%0,%1,%2,%3}, [%4];"
                 : "=r"(r[0]), "=r"(r[1]), "=r"(r[2]), "=r"(r[3]) : "r"(addr));
}

// ---------------- kernel A (s1): per-block relation histogram ----------------
__global__ void k_hist(const int* __restrict__ rel) {
    __shared__ int h[N_REL];
    if (threadIdx.x < N_REL) h[threadIdx.x] = 0;
    __syncthreads();
    int e = blockIdx.x * 256 + threadIdx.x;
    if (e < N_EDGES) {
        int r = rel[e];
        unsigned m = __match_any_sync(__activemask(), r);
        if ((threadIdx.x & 31) == __ffs(m) - 1) atomicAdd(&h[r], __popc(m));
    }
    __syncthreads();
    if (threadIdx.x < N_REL) g_bh[threadIdx.x * NB + blockIdx.x] = h[threadIdx.x];
}

// ---------------- kernel B (s1): scan ----------------
__global__ void k_scan() {   // one block, 320 threads: warp w owns relation w
    __shared__ int s_tot[N_REL];
    __shared__ int s_base[N_REL];
    int w = threadIdx.x >> 5, lane = threadIdx.x & 31;
    if (w < N_REL) {
        int sum = 0;
        for (int i = lane; i < NB; i += 32) sum += g_bh[w * NB + i];
        #pragma unroll
        for (int o = 16; o; o >>= 1) sum += __shfl_xor_sync(~0u, sum, o);
        if (!lane) s_tot[w] = sum;
    }
    __syncthreads();
    if (threadIdx.x == 0) {
        int off = 0, ts = 0;
        for (int r = 0; r < N_REL; r++) {
            s_base[r] = off; g_off[r] = off; g_tile_start[r] = ts;
            off += s_tot[r]; ts += (s_tot[r] + BM - 1) / BM;
        }
        g_off[N_REL] = off; g_tile_start[N_REL] = ts;
    }
    __syncthreads();
    if (w < N_REL) {
        int run = s_base[w];
        for (int base = 0; base < NB; base += 32) {
            int i = base + lane;
            int v = (i < NB) ? g_bh[w * NB + i] : 0;
            int x = v;
            #pragma unroll
            for (int o = 1; o < 32; o <<= 1) {
                int y = __shfl_up_sync(~0u, x, o);
                if (lane >= o) x += y;
            }
            if (i < NB) g_boff[w * NB + i] = run + x - v;
            run += __shfl_sync(~0u, x, 31);
        }
    }
}

// ---------------- kernel C (s1): scatter ----------------
__global__ void k_scatter(const int* __restrict__ rel) {
    __shared__ int cur[N_REL];
    if (threadIdx.x < N_REL)
        cur[threadIdx.x] = g_boff[threadIdx.x * NB + blockIdx.x];
    __syncthreads();
    int e = blockIdx.x * 256 + threadIdx.x;
    if (e < N_EDGES) {
        int lane = threadIdx.x & 31;
        int r = rel[e];
        unsigned m = __match_any_sync(__activemask(), r);
        int leader = __ffs(m) - 1;
        int rank = __popc(m & ((1u << lane) - 1));
        int base = 0;
        if (lane == leader) base = atomicAdd(&cur[r], __popc(m));
        base = __shfl_sync(m, base, leader);
        g_sorted[base + rank] = e;
    }
}

// ---------------- kernel D (s2): x fp16 convert + W n-major transpose --------
__global__ void k_conv(const float* __restrict__ x,
                       const float* __restrict__ W_self,
                       const float* __restrict__ W_fwd,
                       const float* __restrict__ W_rev) {
    __shared__ __half tile[32][33];
    if (blockIdx.x < XVB) {
        int i = blockIdx.x * 256 + threadIdx.x;
        if (i < XV) {
            float4 v = reinterpret_cast<const float4*>(x)[i];
            __half2 lo = __floats2half2_rn(v.x, v.y);
            __half2 hi = __floats2half2_rn(v.z, v.w);
            uint2 o;
            o.x = *reinterpret_cast<uint32_t*>(&lo);
            o.y = *reinterpret_cast<uint32_t*>(&hi);
            reinterpret_cast<uint2*>(g_xh)[i] = o;
        }
    } else {
        int idx = blockIdx.x - XVB;
        int m = idx >> 6, t = idx & 63;
        int tn = t >> 3, tk = t & 7;
        const float* src = (m == 0) ? W_self
                         : (m <= 10) ? W_fwd + (size_t)(m - 1) * DIM * DIM
                                     : W_rev + (size_t)(m - 11) * DIM * DIM;
        int tx = threadIdx.x & 31, ty = threadIdx.x >> 5;   // 32 x 8
        #pragma unroll
        for (int j = 0; j < 4; j++) {
            int k = tk * 32 + ty + j * 8;
            int n = tn * 32 + tx;
            tile[ty + j * 8][tx] = __float2half_rn(src[(size_t)k * DIM + n]);
        }
        __syncthreads();
        __half* dst = g_Wt + (size_t)m * DIM * DIM;
        #pragma unroll
        for (int j = 0; j < 4; j++) {
            int n = tn * 32 + ty + j * 8;
            int k = tk * 32 + tx;
            dst[(size_t)n * DIM + k] = tile[tx][ty + j * 8];
        }
    }
}

// ---------------- kernel E: fused grouped gather-GEMM ----------------
// t0 = tile offset: 0 for self launch (grid x = SELF_TILES),
//                   SELF_TILES for message launch (grid x = 2*MAX_TILES).
__global__ __launch_bounds__(THREADS, 2)
void k_gemm(const float* __restrict__ b_self,
            const float* __restrict__ b_fwd,
            const float* __restrict__ b_rev,
            const int* __restrict__ dep,
            const int* __restrict__ gov,
            float* __restrict__ out,
            int t0)
{
    extern __shared__ char smem[];
    __shared__ int s_src[BM];
    __shared__ int s_dst[BM];

    const int tid  = threadIdx.x;
    const int lane = tid & 31;
    const int warp = tid >> 5;
    const int wm   = warp >> 1;   // 0..3 : 32-row band
    const int wn   = warp & 1;    // 0..1 : 64-col band
    const int nbase = blockIdx.y * BN;

    // ---- tile resolve ----
    int t = blockIdx.x + t0;
    const float* bias;
    const __half* Wt;   // n-major weights, offset to nbase
    if (t < SELF_TILES) {
        Wt = g_Wt + (size_t)nbase * DIM;
        bias = b_self;
        if (tid < BM) {
            int row = t * BM + tid;
            s_src[tid] = (row < N_NODES) ? row : 0;
            s_dst[tid] = (row < N_NODES) ? row : -1;
        }
    } else {
        int T = g_tile_start[N_REL];
        int tm = t - SELF_TILES;
        if (tm >= 2 * T) return;                      // uniform early exit
        int mode = (tm < T) ? 1 : 2;
        int tt = (mode == 1) ? tm : tm - T;
        int g = 0;
        while (tt >= g_tile_start[g + 1]) g++;
        int ebase = g_off[g] + (tt - g_tile_start[g]) * BM;
        int ecnt  = g_off[g + 1] - ebase;
        Wt   = g_Wt + (size_t)(1 + (mode == 2 ? N_REL : 0) + g) * DIM * DIM
                    + (size_t)nbase * DIM;
        bias = ((mode == 1) ? b_fwd : b_rev) + g * DIM;
        if (tid < BM) {
            if (tid < ecnt) {
                int e = g_sorted[ebase + tid];
                s_src[tid] = (mode == 1) ? gov[e] : dep[e];
                s_dst[tid] = (mode == 1) ? dep[e] : gov[e];
            } else {
                s_src[tid] = 0; s_dst[tid] = -1;
            }
        }
    }
    __syncthreads();

    const uint32_t sbase = (uint32_t)__cvta_generic_to_shared(smem);

    // ---- staging: A = 128 rows x 64 fp16 (gathered); B = 128 n-rows x 64 k
    auto prefetch = [&](int stg, int kb) {
        uint32_t As = sbase + stg * STAGE_BYTES;
        uint32_t Bs = As + A_BYTES;
        #pragma unroll
        for (int j = 0; j < 4; j++) {                 // 1024 16B-segs of A
            int i = tid + THREADS * j;
            int row = i >> 3, seg = i & 7;
            cp16(As + row * PA_B + seg * 16,
                 g_xh + (size_t)s_src[row] * DIM + kb * BK + seg * 8);
        }
        #pragma unroll
        for (int j = 0; j < 4; j++) {                 // 1024 16B-segs of B
            int i = tid + THREADS * j;
            int row = i >> 3, seg = i & 7;            // n-row, k-seg
            cp16(Bs + row * PB_B + seg * 16,
                 Wt + (size_t)row * DIM + kb * BK + seg * 8);
        }
    };

    float acc[2][8][4];
    #pragma unroll
    for (int i = 0; i < 2; i++)
        #pragma unroll
        for (int j = 0; j < 8; j++)
            #pragma unroll
            for (int k = 0; k < 4; k++) acc[i][j][k] = 0.0f;

    // ldmatrix per-lane address parts (both non-trans)
    const uint32_t rowA = (wm * 32 + (lane & 15)) * PA_B + (lane >> 4) * 16;
    const uint32_t rowB = (wn * 64 + (lane >> 4) * 8 + (lane & 7)) * PB_B
                          + ((lane >> 3) & 1) * 16;

    prefetch(0, 0); cp_commit();
    prefetch(1, 1); cp_commit();

    #pragma unroll
    for (int kb = 0; kb < NKB; kb++) {
        if (kb + 1 < NKB) cp_wait<1>(); else cp_wait<0>();
        __syncthreads();
        if (kb + 2 < NKB) {
            prefetch((kb + 2) % NSTAGE, kb + 2);
            cp_commit();
        }

        uint32_t As = sbase + (kb % NSTAGE) * STAGE_BYTES;
        uint32_t Bs = As + A_BYTES;

        #pragma unroll
        for (int kk = 0; kk < 4; kk++) {     // four k16 chunks per BK=64
            uint32_t a[2][4];
            ldsm_x4(a[0], As + rowA + kk * 32);             // rows wm*32..+15
            ldsm_x4(a[1], As + rowA + 16 * PA_B + kk * 32); // rows +16..+31
            uint32_t b[4][4];                               // 4 groups of 16 n-cols
            #pragma unroll
            for (int ntg = 0; ntg < 4; ntg++)
                ldsm_x4(b[ntg], Bs + rowB + ntg * (16 * PB_B) + kk * 32);
            #pragma unroll
            for (int mt = 0; mt < 2; mt++)
                #pragma unroll
                for (int nt = 0; nt < 8; nt++)
                    asm volatile(
                        "mma.sync.aligned.m16n8k16.row.col.f32.f16.f16.f32 "
                        "{%0,%1,%2,%3},{%4,%5,%6,%7},{%8,%9},{%0,%1,%2,%3};"
                        : "+f"(acc[mt][nt][0]), "+f"(acc[mt][nt][1]),
                          "+f"(acc[mt][nt][2]), "+f"(acc[mt][nt][3])
                        : "r"(a[mt][0]), "r"(a[mt][1]), "r"(a[mt][2]), "r"(a[mt][3]),
                          "r"(b[nt >> 1][(nt & 1) * 2]),
                          "r"(b[nt >> 1][(nt & 1) * 2 + 1]));
        }
    }

    // ---- epilogue: pair lanes (lane^1 shares the same output row) and issue
    // 128-bit red.global.add.v4.f32 into pre-zeroed out.
    const int gq = lane >> 2;
    const int tg = lane & 3;
    #pragma unroll
    for (int mt = 0; mt < 2; mt++) {
        #pragma unroll
        for (int half = 0; half < 2; half++) {
            int rl = wm * 32 + mt * 16 + gq + half * 8;
            int d  = s_dst[rl];
            #pragma unroll
            for (int nt = 0; nt < 8; nt++) {
                int c  = nbase + wn * 64 + nt * 8 + tg * 2;
                float v0 = acc[mt][nt][half * 2 + 0] + __ldg(&bias[c]);
                float v1 = acc[mt][nt][half * 2 + 1] + __ldg(&bias[c + 1]);
                float s0 = __shfl_xor_sync(0xFFFFFFFFu, v0, 1);
                float s1 = __shfl_xor_sync(0xFFFFFFFFu, v1, 1);
                if (d >= 0 && ((tg ^ nt) & 1) == 0) {
                    float a0, a1, a2, a3;
                    if (tg & 1) { a0 = s0; a1 = s1; a2 = v0; a3 = v1; }
                    else        { a0 = v0; a1 = v1; a2 = s0; a3 = s1; }
                    int c4 = nbase + wn * 64 + nt * 8 + (tg >> 1) * 4;
                    asm volatile("red.global.add.v4.f32 [%0], {%1,%2,%3,%4};"
                                 :: "l"(&out[(size_t)d * DIM + c4]),
                                    "f"(a0), "f"(a1), "f"(a2), "f"(a3)
                                 : "memory");
                }
            }
        }
    }
}

// ---------------- launch: 3-stream dataflow graph ----------------
extern "C" void kernel_launch(void* const* d_in, const int* in_sizes, int n_in,
                              void* d_out, int out_size)
{
    const float* x      = (const float*)d_in[0];
    const float* W_self = (const float*)d_in[1];
    const float* b_self = (const float*)d_in[2];
    const float* W_fwd  = (const float*)d_in[3];
    const float* b_fwd  = (const float*)d_in[4];
    const float* W_rev  = (const float*)d_in[5];
    const float* b_rev  = (const float*)d_in[6];
    const int*   dep    = (const int*)d_in[7];
    const int*   rel    = (const int*)d_in[8];
    const int*   gov    = (const int*)d_in[9];
    float* out = (float*)d_out;

    static bool init_done = false;
    static cudaStream_t s1, s2;
    static cudaEvent_t evFork, evZero, evScat, evConv, evSelf;
    if (!init_done) {
        cudaFuncSetAttribute(k_gemm, cudaFuncAttributeMaxDynamicSharedMemorySize,
                             DSMEM_BYTES);
        cudaStreamCreateWithFlags(&s1, cudaStreamNonBlocking);
        cudaStreamCreateWithFlags(&s2, cudaStreamNonBlocking);
        cudaEventCreateWithFlags(&evFork, cudaEventDisableTiming);
        cudaEventCreateWithFlags(&evZero, cudaEventDisableTiming);
        cudaEventCreateWithFlags(&evScat, cudaEventDisableTiming);
        cudaEventCreateWithFlags(&evConv, cudaEventDisableTiming);
        cudaEventCreateWithFlags(&evSelf, cudaEventDisableTiming);
        init_done = true;
    }

    // fork both side streams from the capture origin
    cudaEventRecord(evFork, 0);
    cudaStreamWaitEvent(s1, evFork, 0);
    cudaStreamWaitEvent(s2, evFork, 0);

    // s0: zero the output (needed by both GEMM launches)
    cudaMemsetAsync(d_out, 0, (size_t)out_size * sizeof(float));
    cudaEventRecord(evZero, 0);

    // s1: sort chain
    k_hist<<<NB, 256, 0, s1>>>(rel);
    k_scan<<<1, 320, 0, s1>>>();
    k_scatter<<<NB, 256, 0, s1>>>(rel);
    cudaEventRecord(evScat, s1);

    // s2: convert, then self-GEMM (no sort dependency)
    k_conv<<<XVB + WTB, 256, 0, s2>>>(x, W_self, W_fwd, W_rev);
    cudaEventRecord(evConv, s2);
    cudaStreamWaitEvent(s2, evZero, 0);
    k_gemm<<<dim3(SELF_TILES, 2), THREADS, DSMEM_BYTES, s2>>>(
        b_self, b_fwd, b_rev, dep, gov, out, 0);
    cudaEventRecord(evSelf, s2);

    // s0: message GEMM after zero + conv + scatter
    cudaStreamWaitEvent(0, evConv, 0);
    cudaStreamWaitEvent(0, evScat, 0);
    k_gemm<<<dim3(2 * MAX_TILES, 2), THREADS, DSMEM_BYTES>>>(
        b_self, b_fwd, b_rev, dep, gov, out, SELF_TILES);

    // join s2 back into the capture stream
    cudaStreamWaitEvent(0, evSelf, 0);
}